// round 1
// baseline (speedup 1.0000x reference)
#include <cuda_runtime.h>
#include <cuda_bf16.h>

// Problem constants (fixed by setup_inputs)
#define B_    32
#define N_    8192
#define HD    256     // H_DIM
#define GH    512     // G_HID
#define GD    256     // G_DIM
#define KC    64      // K
#define CHUNK (N_/KC) // 128 positions per cluster
#define ROWS  (2*KC+1)     // 129 MLP rows per batch
#define M_TOT (B_*ROWS)    // 4128

// Scratch (static device globals — no allocation allowed)
__device__ float d_H [M_TOT * HD];   // 4.2 MB
__device__ float d_h1[M_TOT * GH];   // 8.4 MB
__device__ float d_gs[M_TOT * GD];   // 4.2 MB

// ---------------------------------------------------------------------------
// Kernel 1: clustered reduction, directly materializing all 129 H rows/batch.
//   row j<K      : Hk[b,j]
//   row K<=j<2K  : Hk[b,j-K] + hn[b]
//   row 2K       : hn[b]
// Grid (K, B), 256 threads (one per h).
// ---------------------------------------------------------------------------
__global__ void reduce_kernel(const float* __restrict__ hs,
                              const int*   __restrict__ cs,
                              const int*   __restrict__ n_ptr)
{
    const int k = blockIdx.x;
    const int b = blockIdx.y;
    const int h = threadIdx.x;
    const int n = *n_ptr;

    const int base = k * CHUNK;
    const float* p = hs + ((size_t)b * N_ + base) * HD + h;

    float s = 0.f;
#pragma unroll 8
    for (int i = 0; i < CHUNK; ++i) {
        const int idx = base + i;
        if (idx < n && cs[idx] == k)
            s += p[(size_t)i * HD];
    }
    const float hv = hs[((size_t)b * N_ + n) * HD + h];

    d_H[(size_t)(b * ROWS + k)      * HD + h] = s;
    d_H[(size_t)(b * ROWS + KC + k) * HD + h] = s + hv;
    if (k == 0)
        d_H[(size_t)(b * ROWS + 2 * KC) * HD + h] = hv;
}

// ---------------------------------------------------------------------------
// Kernels 2/3: fp32 tiled GEMM  C[M,N] = act(A[M,K] @ W[K,N] + bias)
// 64x64 tile, BK=16, 256 threads, 4x4 per thread. Weights fit in L2.
// ---------------------------------------------------------------------------
template<bool RELU>
__global__ void gemm_kernel(const float* __restrict__ A,
                            const float* __restrict__ W,
                            const float* __restrict__ bias,
                            float* __restrict__ C,
                            int M, int Nn, int Kk)
{
    constexpr int BM = 64, BN = 64, BK = 16;
    __shared__ float As[BK][BM + 4];   // +4 pad keeps float4 alignment, cuts conflicts
    __shared__ float Bs[BK][BN];

    const int tid = threadIdx.x;
    const int tx  = tid & 15;          // 0..15  -> 4 cols each
    const int ty  = tid >> 4;          // 0..15  -> 4 rows each
    const int m0  = blockIdx.y * BM;
    const int n0  = blockIdx.x * BN;

    float acc[4][4] = {};

    for (int k0 = 0; k0 < Kk; k0 += BK) {
        // Load A tile (BM x BK), stored transposed As[kk][mm]
#pragma unroll
        for (int i = 0; i < (BM * BK) / 256; ++i) {
            const int idx = tid + i * 256;
            const int mm  = idx / BK;
            const int kk  = idx % BK;
            const int gm  = m0 + mm;
            As[kk][mm] = (gm < M) ? A[(size_t)gm * Kk + k0 + kk] : 0.f;
        }
        // Load B tile (BK x BN), coalesced
#pragma unroll
        for (int i = 0; i < (BK * BN) / 256; ++i) {
            const int idx = tid + i * 256;
            const int kk  = idx / BN;
            const int nn  = idx % BN;
            Bs[kk][nn] = W[(size_t)(k0 + kk) * Nn + n0 + nn];
        }
        __syncthreads();

#pragma unroll
        for (int kk = 0; kk < BK; ++kk) {
            const float4 av = *(const float4*)&As[kk][ty * 4];
            const float4 bv = *(const float4*)&Bs[kk][tx * 4];
            const float a[4] = {av.x, av.y, av.z, av.w};
            const float bb[4] = {bv.x, bv.y, bv.z, bv.w};
#pragma unroll
            for (int i = 0; i < 4; ++i)
#pragma unroll
                for (int j = 0; j < 4; ++j)
                    acc[i][j] += a[i] * bb[j];
        }
        __syncthreads();
    }

#pragma unroll
    for (int i = 0; i < 4; ++i) {
        const int gm = m0 + ty * 4 + i;
        if (gm >= M) continue;
#pragma unroll
        for (int j = 0; j < 4; ++j) {
            const int gn = n0 + tx * 4 + j;
            float v = acc[i][j] + bias[gn];
            if (RELU) v = fmaxf(v, 0.f);
            C[(size_t)gm * Nn + gn] = v;
        }
    }
}

// ---------------------------------------------------------------------------
// Kernel 4: S = sum_{j<K} gs[b,j,:];  G_front / G_last;  G_mask = 1
// Output layout: G (B*(K+1)*GD floats) followed by G_mask (B*(K+1) floats).
// Grid (B), 256 threads.
// ---------------------------------------------------------------------------
__global__ void finalize_kernel(float* __restrict__ out)
{
    const int b = blockIdx.x;
    const int h = threadIdx.x;
    const float* g = d_gs + (size_t)b * ROWS * GD;

    float S = 0.f;
#pragma unroll 8
    for (int j = 0; j < KC; ++j)
        S += g[(size_t)j * GD + h];

    float* o = out + (size_t)b * (KC + 1) * GD;
#pragma unroll 4
    for (int k = 0; k < KC; ++k)
        o[(size_t)k * GD + h] = S - g[(size_t)k * GD + h] + g[(size_t)(KC + k) * GD + h];
    o[(size_t)KC * GD + h] = S + g[(size_t)(2 * KC) * GD + h];

    // mask
    float* mask = out + (size_t)B_ * (KC + 1) * GD;
    if (h <= KC)
        mask[b * (KC + 1) + h] = 1.0f;
}

// ---------------------------------------------------------------------------
extern "C" void kernel_launch(void* const* d_in, const int* in_sizes, int n_in,
                              void* d_out, int out_size)
{
    const float* hs = (const float*)d_in[0];
    const int*   cs = (const int*)  d_in[1];   // cs_o; first N entries are row 0
    const float* W1 = (const float*)d_in[2];
    const float* b1 = (const float*)d_in[3];
    const float* W2 = (const float*)d_in[4];
    const float* b2 = (const float*)d_in[5];
    const int*   np = (const int*)  d_in[6];   // n (scalar)
    float* out = (float*)d_out;

    float *pH, *pH1, *pGS;
    cudaGetSymbolAddress((void**)&pH,  d_H);
    cudaGetSymbolAddress((void**)&pH1, d_h1);
    cudaGetSymbolAddress((void**)&pGS, d_gs);

    // 1. clustered reduce + H materialization
    reduce_kernel<<<dim3(KC, B_), HD>>>(hs, cs, np);

    // 2. layer 1: [4128,256] @ [256,512] + b1, relu
    gemm_kernel<true ><<<dim3(GH / 64, (M_TOT + 63) / 64), 256>>>(pH,  W1, b1, pH1, M_TOT, GH, HD);

    // 3. layer 2: [4128,512] @ [512,256] + b2
    gemm_kernel<false><<<dim3(GD / 64, (M_TOT + 63) / 64), 256>>>(pH1, W2, b2, pGS, M_TOT, GD, GH);

    // 4. S, G, mask
    finalize_kernel<<<B_, HD>>>(out);
}

// round 2
// speedup vs baseline: 1.6766x; 1.6766x over previous
#include <cuda_runtime.h>
#include <cuda_bf16.h>

// Problem constants (fixed by setup_inputs)
#define B_    32
#define N_    8192
#define HD    256     // H_DIM
#define GH    512     // G_HID
#define GD    256     // G_DIM
#define KC    64      // K
#define CHUNK (N_/KC) // 128 positions per cluster
#define ROWS  (2*KC+1)     // 129 MLP rows per batch
#define M_TOT (B_*ROWS)    // 4128

typedef unsigned long long u64;

// Scratch (static device globals — no allocation allowed)
__device__ float d_H  [M_TOT * HD];        // 4.2 MB
__device__ float d_h1 [M_TOT * GH];        // 8.4 MB
__device__ float d_gs [2 * M_TOT * GD];    // 8.4 MB (split-K partials)
__device__ float d_Sp [4 * B_ * GD];       // partial S

// ---------------------------------------------------------------------------
// packed f32x2 helpers (ptxas never emits FFMA2 from C++; PTX-only path)
// ---------------------------------------------------------------------------
__device__ __forceinline__ u64 dup2(float x) {
    unsigned xi = __float_as_uint(x);
    u64 r;
    asm("mov.b64 %0, {%1, %1};" : "=l"(r) : "r"(xi));
    return r;
}
__device__ __forceinline__ void ffma2(u64& d, u64 a, u64 b) {
    asm("fma.rn.f32x2 %0, %1, %2, %0;" : "+l"(d) : "l"(a), "l"(b));
}
__device__ __forceinline__ float2 unpk(u64 v) {
    unsigned lo, hi;
    asm("mov.b64 {%0, %1}, %2;" : "=r"(lo), "=r"(hi) : "l"(v));
    return make_float2(__uint_as_float(lo), __uint_as_float(hi));
}

// ---------------------------------------------------------------------------
// Kernel 1: clustered reduction (float4-vectorized, 4 row groups per block).
// Grid (K, B), 256 threads. Rows of d_H:
//   j<K: Hk[b,j];  K<=j<2K: Hk+hn;  2K: hn
// ---------------------------------------------------------------------------
__global__ void reduce_kernel(const float* __restrict__ hs,
                              const int*   __restrict__ cs,
                              const int*   __restrict__ n_ptr)
{
    const int k    = blockIdx.x;
    const int b    = blockIdx.y;
    const int tid  = threadIdx.x;
    const int lane = tid & 63;    // h/4
    const int grp  = tid >> 6;    // 0..3
    const int n    = *n_ptr;
    const int base = k * CHUNK;

    const float* p = hs + ((size_t)b * N_ + base) * HD + lane * 4;

    float4 s = make_float4(0.f, 0.f, 0.f, 0.f);
#pragma unroll 8
    for (int i = grp; i < CHUNK; i += 4) {
        const int idx = base + i;
        if (idx < n && cs[idx] == k) {
            float4 v = *(const float4*)(p + (size_t)i * HD);
            s.x += v.x; s.y += v.y; s.z += v.z; s.w += v.w;
        }
    }

    __shared__ float4 sm[4][64];
    sm[grp][lane] = s;
    __syncthreads();

    if (grp == 0) {
        float4 t = sm[0][lane];
        float4 u1 = sm[1][lane], u2 = sm[2][lane], u3 = sm[3][lane];
        t.x += u1.x + u2.x + u3.x;
        t.y += u1.y + u2.y + u3.y;
        t.z += u1.z + u2.z + u3.z;
        t.w += u1.w + u2.w + u3.w;

        float4 hv = *(const float4*)(hs + ((size_t)b * N_ + n) * HD + lane * 4);

        float4* rowA = (float4*)(d_H + (size_t)(b * ROWS + k)      * HD) + lane;
        float4* rowB = (float4*)(d_H + (size_t)(b * ROWS + KC + k) * HD) + lane;
        *rowA = t;
        *rowB = make_float4(t.x + hv.x, t.y + hv.y, t.z + hv.z, t.w + hv.w);
        if (k == 0)
            ((float4*)(d_H + (size_t)(b * ROWS + 2 * KC) * HD))[lane] = hv;
    }
}

// ---------------------------------------------------------------------------
// Kernels 2/3: fp32 GEMM, 128x128 tile, BK=16, 256 threads, 8x8/thread,
// packed f32x2 accumulators. blockIdx.z selects a 256-wide K slice; output
// goes to C + z*M*Nn (split-K partials); bias added only on z==0.
// ---------------------------------------------------------------------------
template<bool RELU>
__global__ __launch_bounds__(256)
void gemm_kernel(const float* __restrict__ A,
                 const float* __restrict__ W,
                 const float* __restrict__ bias,
                 float* __restrict__ C,
                 int M, int Nn, int Ktot)
{
    constexpr int BM = 128, BN = 128, BK = 16;
    __shared__ float As[BK][BM + 4];
    __shared__ float Bs[BK][BN + 4];

    const int tid = threadIdx.x;
    const int tx  = tid & 15;     // 8 cols each
    const int ty  = tid >> 4;     // 8 rows each
    const int m0  = blockIdx.y * BM;
    const int n0  = blockIdx.x * BN;
    const int kbase = blockIdx.z * 256;      // split-K slice start
    const int kend  = kbase + 256;           // each slice is 256 deep (Ktot>=kend)

    // A-tile loader mapping: 2 threads per row, 8 K-floats each
    const int ar = tid >> 1;
    const int ac = (tid & 1) * 8;
    // B-tile loader mapping: 16 threads per K-row, 8 N-floats each
    const int bk = tid >> 4;
    const int bn = (tid & 15) * 8;

    u64 acc[8][4];
#pragma unroll
    for (int i = 0; i < 8; ++i)
#pragma unroll
        for (int j = 0; j < 4; ++j) acc[i][j] = 0ull;

    for (int k0 = kbase; k0 < kend; k0 += BK) {
        // load A tile (transposed into As[kk][mm])
        {
            const int gm = m0 + ar;
            float4 v0 = make_float4(0.f,0.f,0.f,0.f), v1 = v0;
            if (gm < M) {
                const float* ap = A + (size_t)gm * Ktot + k0 + ac;
                v0 = *(const float4*)ap;
                v1 = *(const float4*)(ap + 4);
            }
            As[ac+0][ar] = v0.x; As[ac+1][ar] = v0.y;
            As[ac+2][ar] = v0.z; As[ac+3][ar] = v0.w;
            As[ac+4][ar] = v1.x; As[ac+5][ar] = v1.y;
            As[ac+6][ar] = v1.z; As[ac+7][ar] = v1.w;
        }
        // load B tile (coalesced)
        {
            const float* wp = W + (size_t)(k0 + bk) * Nn + n0 + bn;
            *(float4*)&Bs[bk][bn]     = *(const float4*)wp;
            *(float4*)&Bs[bk][bn + 4] = *(const float4*)(wp + 4);
        }
        __syncthreads();

#pragma unroll
        for (int kk = 0; kk < BK; ++kk) {
            float4 a0 = *(const float4*)&As[kk][ty * 8];
            float4 a1 = *(const float4*)&As[kk][ty * 8 + 4];
            const u64* bp = (const u64*)&Bs[kk][tx * 8];
            const u64 b0 = bp[0], b1 = bp[1], b2 = bp[2], b3 = bp[3];

            u64 ad;
            ad = dup2(a0.x); ffma2(acc[0][0],ad,b0); ffma2(acc[0][1],ad,b1); ffma2(acc[0][2],ad,b2); ffma2(acc[0][3],ad,b3);
            ad = dup2(a0.y); ffma2(acc[1][0],ad,b0); ffma2(acc[1][1],ad,b1); ffma2(acc[1][2],ad,b2); ffma2(acc[1][3],ad,b3);
            ad = dup2(a0.z); ffma2(acc[2][0],ad,b0); ffma2(acc[2][1],ad,b1); ffma2(acc[2][2],ad,b2); ffma2(acc[2][3],ad,b3);
            ad = dup2(a0.w); ffma2(acc[3][0],ad,b0); ffma2(acc[3][1],ad,b1); ffma2(acc[3][2],ad,b2); ffma2(acc[3][3],ad,b3);
            ad = dup2(a1.x); ffma2(acc[4][0],ad,b0); ffma2(acc[4][1],ad,b1); ffma2(acc[4][2],ad,b2); ffma2(acc[4][3],ad,b3);
            ad = dup2(a1.y); ffma2(acc[5][0],ad,b0); ffma2(acc[5][1],ad,b1); ffma2(acc[5][2],ad,b2); ffma2(acc[5][3],ad,b3);
            ad = dup2(a1.z); ffma2(acc[6][0],ad,b0); ffma2(acc[6][1],ad,b1); ffma2(acc[6][2],ad,b2); ffma2(acc[6][3],ad,b3);
            ad = dup2(a1.w); ffma2(acc[7][0],ad,b0); ffma2(acc[7][1],ad,b1); ffma2(acc[7][2],ad,b2); ffma2(acc[7][3],ad,b3);
        }
        __syncthreads();
    }

    // epilogue
    float* Cz = C + (size_t)blockIdx.z * M * Nn;
    const bool add_bias = (blockIdx.z == 0);
    const int gn0 = n0 + tx * 8;
#pragma unroll
    for (int i = 0; i < 8; ++i) {
        const int gm = m0 + ty * 8 + i;
        if (gm >= M) continue;
        float o[8];
#pragma unroll
        for (int j = 0; j < 4; ++j) {
            float2 p = unpk(acc[i][j]);
            o[2*j] = p.x; o[2*j+1] = p.y;
        }
        if (add_bias) {
#pragma unroll
            for (int j = 0; j < 8; ++j) o[j] += bias[gn0 + j];
        }
        if (RELU) {
#pragma unroll
            for (int j = 0; j < 8; ++j) o[j] = fmaxf(o[j], 0.f);
        }
        float* cp = Cz + (size_t)gm * Nn + gn0;
        *(float4*)cp       = make_float4(o[0], o[1], o[2], o[3]);
        *(float4*)(cp + 4) = make_float4(o[4], o[5], o[6], o[7]);
    }
}

// ---------------------------------------------------------------------------
// Kernel 4a: partial S. Grid (4, B). Block (q,b) sums gs rows j=q*16..q*16+15
// over both split-K partials into d_Sp[q][b][:].
// ---------------------------------------------------------------------------
__global__ void s_partial_kernel()
{
    const int q = blockIdx.x;
    const int b = blockIdx.y;
    const int h = threadIdx.x;
    const float* g0 = d_gs + (size_t)b * ROWS * GD;
    const float* g1 = g0 + (size_t)M_TOT * GD;

    float s = 0.f;
#pragma unroll
    for (int j = q * 16; j < q * 16 + 16; ++j) {
        s += g0[(size_t)j * GD + h] + g1[(size_t)j * GD + h];
    }
    d_Sp[((size_t)q * B_ + b) * GD + h] = s;
}

// ---------------------------------------------------------------------------
// Kernel 4b: finalize. Grid (K+1, B), 256 threads.
// ---------------------------------------------------------------------------
__global__ void finalize_kernel(float* __restrict__ out)
{
    const int k = blockIdx.x;     // 0..K
    const int b = blockIdx.y;
    const int h = threadIdx.x;

    float S = d_Sp[((size_t)0 * B_ + b) * GD + h]
            + d_Sp[((size_t)1 * B_ + b) * GD + h]
            + d_Sp[((size_t)2 * B_ + b) * GD + h]
            + d_Sp[((size_t)3 * B_ + b) * GD + h];

    const float* g0 = d_gs + (size_t)b * ROWS * GD;
    const float* g1 = g0 + (size_t)M_TOT * GD;

    float v;
    if (k < KC) {
        float gk  = g0[(size_t)k * GD + h]        + g1[(size_t)k * GD + h];
        float gKk = g0[(size_t)(KC + k) * GD + h] + g1[(size_t)(KC + k) * GD + h];
        v = S - gk + gKk;
    } else {
        float gl = g0[(size_t)(2 * KC) * GD + h] + g1[(size_t)(2 * KC) * GD + h];
        v = S + gl;
    }
    out[((size_t)b * (KC + 1) + k) * GD + h] = v;

    if (h == 0)
        out[(size_t)B_ * (KC + 1) * GD + b * (KC + 1) + k] = 1.0f;  // G_mask
}

// ---------------------------------------------------------------------------
extern "C" void kernel_launch(void* const* d_in, const int* in_sizes, int n_in,
                              void* d_out, int out_size)
{
    const float* hs = (const float*)d_in[0];
    const int*   cs = (const int*)  d_in[1];
    const float* W1 = (const float*)d_in[2];
    const float* b1 = (const float*)d_in[3];
    const float* W2 = (const float*)d_in[4];
    const float* b2 = (const float*)d_in[5];
    const int*   np = (const int*)  d_in[6];
    float* out = (float*)d_out;

    float *pH, *pH1, *pGS;
    cudaGetSymbolAddress((void**)&pH,  d_H);
    cudaGetSymbolAddress((void**)&pH1, d_h1);
    cudaGetSymbolAddress((void**)&pGS, d_gs);

    // 1. clustered reduce + H materialization
    reduce_kernel<<<dim3(KC, B_), 256>>>(hs, cs, np);

    // 2. layer 1: [4128,256]@[256,512]+b1, relu  (132 blocks, 1 wave)
    gemm_kernel<true ><<<dim3(GH / 128, (M_TOT + 127) / 128, 1), 256>>>(pH,  W1, b1, pH1, M_TOT, GH, HD);

    // 3. layer 2: [4128,512]@[512,256]+b2, split-K=2 (132 blocks)
    gemm_kernel<false><<<dim3(GD / 128, (M_TOT + 127) / 128, 2), 256>>>(pH1, W2, b2, pGS, M_TOT, GD, GH);

    // 4. S partials + finalize
    s_partial_kernel<<<dim3(4, B_), 256>>>();
    finalize_kernel<<<dim3(KC + 1, B_), 256>>>(out);
}